// round 15
// baseline (speedup 1.0000x reference)
#include <cuda_runtime.h>
#include <cuda_bf16.h>
#include <cuda_fp16.h>
#include <math.h>
#include <float.h>
#include <stdint.h>

// Problem constants
#define BB 2
#define NN 2048
#define CC 512
#define HH 8
#define DD 64
#define FF 1536   // 3*H*D

// ==================== scratch (device globals) ====================
__device__ float g_v[BB * HH * NN * DD];
__device__ __align__(256) __half g_dots[(size_t)BB * HH * NN * NN];   // 128 MiB fp16
__device__ __align__(256) __nv_bfloat16 g_xh[BB * NN * CC];
__device__ __align__(256) __nv_bfloat16 g_xl[BB * NN * CC];
__device__ __align__(256) __nv_bfloat16 g_wqh[FF * CC];        // permuted f' = s*512+h*64+d
__device__ __align__(256) __nv_bfloat16 g_wql[FF * CC];
__device__ __align__(256) __nv_bfloat16 g_woh[CC * HH * DD];
__device__ __align__(256) __nv_bfloat16 g_wol[CC * HH * DD];
__device__ __align__(256) __half g_qs[BB * HH * NN * DD];      // fp16 single (scale folded)
__device__ __align__(256) __half g_ks[BB * HH * NN * DD];      // fp16 single
__device__ __align__(256) __half g_posh[HH * NN * NN];         // fp16 pos bias (64 MiB)
__device__ __align__(256) __half g_vt[BB * HH * DD * NN];      // [bh][d][n] fp16 single
__device__ __align__(256) __half g_attn[(size_t)BB * HH * NN * NN];   // 128 MiB fp16 single
__device__ __align__(256) __nv_bfloat16 g_outf_hi[BB * NN * (HH * DD)];
__device__ __align__(256) __nv_bfloat16 g_outf_lo[BB * NN * (HH * DD)];

// ==================== helpers ====================
__device__ __forceinline__ uint32_t smem_u32(const void* p) {
    uint32_t a;
    asm("{ .reg .u64 t; cvta.to.shared.u64 t, %1; cvt.u32.u64 %0, t; }" : "=r"(a) : "l"(p));
    return a;
}
__device__ __forceinline__ uint32_t sw64(uint32_t off)  { return off ^ ((off >> 3) & 0x30); }
__device__ __forceinline__ uint32_t sw128(uint32_t off) { return off ^ ((off >> 3) & 0x70); }

__device__ __forceinline__ void ldsm4(uint32_t (&r)[4], uint32_t addr) {
    asm volatile("ldmatrix.sync.aligned.m8n8.x4.shared.b16 {%0,%1,%2,%3}, [%4];"
        : "=r"(r[0]), "=r"(r[1]), "=r"(r[2]), "=r"(r[3]) : "r"(addr));
}
__device__ __forceinline__ void mma16816(float (&c)[4], const uint32_t (&a)[4],
                                         uint32_t b0, uint32_t b1) {
    asm volatile("mma.sync.aligned.m16n8k16.row.col.f32.bf16.bf16.f32 "
        "{%0,%1,%2,%3}, {%4,%5,%6,%7}, {%8,%9}, {%0,%1,%2,%3};"
        : "+f"(c[0]), "+f"(c[1]), "+f"(c[2]), "+f"(c[3])
        : "r"(a[0]), "r"(a[1]), "r"(a[2]), "r"(a[3]), "r"(b0), "r"(b1));
}
__device__ __forceinline__ void mma16816h(float (&c)[4], const uint32_t (&a)[4],
                                          uint32_t b0, uint32_t b1) {
    asm volatile("mma.sync.aligned.m16n8k16.row.col.f32.f16.f16.f32 "
        "{%0,%1,%2,%3}, {%4,%5,%6,%7}, {%8,%9}, {%0,%1,%2,%3};"
        : "+f"(c[0]), "+f"(c[1]), "+f"(c[2]), "+f"(c[3])
        : "r"(a[0]), "r"(a[1]), "r"(a[2]), "r"(a[3]), "r"(b0), "r"(b1));
}
__device__ __forceinline__ void cp16(uint32_t saddr, const void* gptr) {
    asm volatile("cp.async.cg.shared.global [%0], [%1], 16;" :: "r"(saddr), "l"(gptr));
}
#define CP_COMMIT() asm volatile("cp.async.commit_group;" ::: "memory")
__device__ __forceinline__ void cp_wait_dyn(int pend) {
    if (pend >= 2)      asm volatile("cp.async.wait_group 2;" ::: "memory");
    else if (pend == 1) asm volatile("cp.async.wait_group 1;" ::: "memory");
    else                asm volatile("cp.async.wait_group 0;" ::: "memory");
}

// ==================== bf16 pipelined core (CTA 128x64, Kc=32, SW64) ===========
#define SA_H 0
#define SA_L 8192
#define SB_H 16384
#define SB_L 20480
#define ST_STRIDE 24576
#define PIPE_SMEM (3 * ST_STRIDE)

__device__ __forceinline__ void load_stage(
    uint32_t st, const __nv_bfloat16* __restrict__ AH, const __nv_bfloat16* __restrict__ AL,
    int lda, int m0, const __nv_bfloat16* __restrict__ BH, const __nv_bfloat16* __restrict__ BL,
    int ldb, int n0, int k0)
{
    const int t = threadIdx.x;
#pragma unroll
    for (int rep = 0; rep < 2; ++rep) {
        int idx = t + rep * 256;
        int r = idx >> 2, c4 = idx & 3;
        uint32_t off = sw64(r * 64 + c4 * 16);
        size_t ga = (size_t)(m0 + r) * lda + k0 + c4 * 8;
        cp16(st + SA_H + off, AH + ga);
        cp16(st + SA_L + off, AL + ga);
    }
    {
        int r = t >> 2, c4 = t & 3;
        uint32_t off = sw64(r * 64 + c4 * 16);
        size_t gb = (size_t)(n0 + r) * ldb + k0 + c4 * 8;
        cp16(st + SB_H + off, BH + gb);
        cp16(st + SB_L + off, BL + gb);
    }
}

__device__ __forceinline__ void compute_stage(uint32_t st, float (&acc)[2][4][4],
                                              int lane, int wm, int wn)
{
#pragma unroll
    for (int ks = 0; ks < 2; ++ks) {
        uint32_t aH[2][4], aL[2][4];
#pragma unroll
        for (int mt = 0; mt < 2; ++mt) {
            uint32_t row = wm + mt * 16 + (lane & 15);
            uint32_t so = sw64(row * 64 + ks * 32 + (lane >> 4) * 16);
            ldsm4(aH[mt], st + SA_H + so);
            ldsm4(aL[mt], st + SA_L + so);
        }
        uint32_t bH[2][4], bL[2][4];
#pragma unroll
        for (int np = 0; np < 2; ++np) {
            uint32_t row = wn + np * 16 + (lane & 7) + ((lane >> 4) << 3);
            uint32_t so = sw64(row * 64 + ks * 32 + ((lane >> 3) & 1) * 16);
            ldsm4(bH[np], st + SB_H + so);
            ldsm4(bL[np], st + SB_L + so);
        }
#pragma unroll
        for (int mt = 0; mt < 2; ++mt)
#pragma unroll
            for (int nt = 0; nt < 4; ++nt) {
                uint32_t b0h = bH[nt >> 1][(nt & 1) * 2], b1h = bH[nt >> 1][(nt & 1) * 2 + 1];
                uint32_t b0l = bL[nt >> 1][(nt & 1) * 2], b1l = bL[nt >> 1][(nt & 1) * 2 + 1];
                mma16816(acc[mt][nt], aH[mt], b0h, b1h);
                mma16816(acc[mt][nt], aH[mt], b0l, b1l);
                mma16816(acc[mt][nt], aL[mt], b0h, b1h);
            }
    }
}

__device__ __forceinline__ void mma_pipeline(
    const __nv_bfloat16* __restrict__ AH, const __nv_bfloat16* __restrict__ AL, int lda, int m0,
    const __nv_bfloat16* __restrict__ BH, const __nv_bfloat16* __restrict__ BL, int ldb, int n0,
    int K, uint32_t sb, float (&acc)[2][4][4], int lane, int wm, int wn)
{
    const int nk = K / 32;
    load_stage(sb, AH, AL, lda, m0, BH, BL, ldb, n0, 0);
    CP_COMMIT();
    if (nk > 1) {
        load_stage(sb + ST_STRIDE, AH, AL, lda, m0, BH, BL, ldb, n0, 32);
        CP_COMMIT();
    }
    for (int kc = 0; kc < nk; ++kc) {
        if (kc + 2 < nk) {
            load_stage(sb + ((kc + 2) % 3) * ST_STRIDE, AH, AL, lda, m0, BH, BL, ldb, n0,
                       (kc + 2) * 32);
            CP_COMMIT();
        }
        int pend = (nk < kc + 3 ? nk : kc + 3) - (kc + 1);
        cp_wait_dyn(pend);
        __syncthreads();
        compute_stage(sb + (kc % 3) * ST_STRIDE, acc, lane, wm, wn);
        __syncthreads();
    }
}

// ---------------- K0a: plain split fp32 -> bf16 hi/lo ----------------
__global__ void split_kernel(const float* __restrict__ in, __nv_bfloat16* __restrict__ hi,
                             __nv_bfloat16* __restrict__ lo, int n)
{
    int i = blockIdx.x * 256 + threadIdx.x;
    if (i < n) {
        float v = in[i];
        __nv_bfloat16 h = __float2bfloat16(v);
        hi[i] = h;
        lo[i] = __float2bfloat16(v - __bfloat162float(h));
    }
}

// ---------------- K0b: permuted+scaled split of Wqkv ----------------
__global__ void split_wqkv_kernel(const float* __restrict__ W,
                                  __nv_bfloat16* __restrict__ hi, __nv_bfloat16* __restrict__ lo)
{
    int i = blockIdx.x * 256 + threadIdx.x;
    if (i < FF * CC) {
        int f = i >> 9;
        int c = i & 511;
        int h = f / 192;
        int r = f - h * 192;
        int d = r / 3;
        int s = r - d * 3;
        int fp = s * 512 + h * 64 + d;
        float v = W[i] * (s == 0 ? 0.125f : 1.0f);
        __nv_bfloat16 hb = __float2bfloat16(v);
        hi[fp * 512 + c] = hb;
        lo[fp * 512 + c] = __float2bfloat16(v - __bfloat162float(hb));
    }
}

// ---------------- K0c: pos fp32 -> fp16 ----------------
__global__ void convert_pos_kernel(const float* __restrict__ P, __half* __restrict__ Ph, int n)
{
    int i = blockIdx.x * 256 + threadIdx.x;
    if (i < n) Ph[i] = __float2half(P[i]);
}

// ---------------- K1: QKV projection + coalesced scatter ----------------
__global__ __launch_bounds__(256, 2)
void qkv_mma_kernel(const __nv_bfloat16* __restrict__ XH, const __nv_bfloat16* __restrict__ XL,
                    const __nv_bfloat16* __restrict__ WH, const __nv_bfloat16* __restrict__ WL,
                    __half* __restrict__ Q, __half* __restrict__ K,
                    float* __restrict__ V)
{
    extern __shared__ __align__(128) char smem[];
    const uint32_t sb = smem_u32(smem);
    const int m0 = blockIdx.y * 128;
    const int n0 = blockIdx.x * 64;
    const int s = n0 >> 9;
    const int h = (n0 >> 6) & 7;
    const int lane = threadIdx.x & 31, warp = threadIdx.x >> 5;
    const int wm = (warp & 3) * 32, wn = (warp >> 2) * 32;
    float acc[2][4][4] = {};
    mma_pipeline(XH, XL, CC, m0, WH, WL, CC, n0, CC, sb, acc, lane, wm, wn);

#pragma unroll
    for (int mt = 0; mt < 2; ++mt) {
#pragma unroll
        for (int half = 0; half < 2; ++half) {
            int m = m0 + wm + mt * 16 + (lane >> 2) + half * 8;
            int b = m >> 11, n = m & 2047;
            size_t base = (((size_t)b * HH + h) * NN + n) * DD;
#pragma unroll
            for (int nt = 0; nt < 4; ++nt) {
                int d = wn + nt * 8 + (lane & 3) * 2;
                float v0 = acc[mt][nt][half * 2 + 0];
                float v1 = acc[mt][nt][half * 2 + 1];
                if (s == 2) {
                    *(float2*)(V + base + d) = make_float2(v0, v1);
                } else {
                    __half2 hp; hp.x = __float2half(v0); hp.y = __float2half(v1);
                    if (s == 0) *(__half2*)(Q + base + d) = hp;
                    else        *(__half2*)(K + base + d) = hp;
                }
            }
        }
    }
}

// ---------------- K1b: transpose V -> vt (fp16 single) -----------------------
__global__ void convert_v_kernel(const float* __restrict__ V, __half* __restrict__ VT)
{
    __shared__ float ts[64][65];
    const int bh = blockIdx.y;
    const int n0 = blockIdx.x * 64;
    const int t = threadIdx.x;
    const size_t base = ((size_t)bh * NN + n0) * DD;
    for (int idx = t; idx < 64 * 64; idx += 256)
        ts[idx >> 6][idx & 63] = V[base + idx];
    __syncthreads();
    for (int idx = t; idx < 64 * 64; idx += 256) {
        int d = idx >> 6, c = idx & 63;
        VT[((size_t)bh * DD + d) * NN + n0 + c] = __float2half(ts[c][d]);
    }
}

// ---------------- K2: dots = q(f16) @ k(f16)^T, 1 combo ----------------------
#define DT_A 0
#define DT_B 16384
#define DK_SMEM 32768

__global__ __launch_bounds__(256, 2)
void dots_mma_kernel(const __half* __restrict__ Q, const __half* __restrict__ K,
                     __half* __restrict__ Dots)
{
    extern __shared__ __align__(128) char smem[];
    const uint32_t sb = smem_u32(smem);
    const int t = threadIdx.x;
    const int lane = t & 31, warp = t >> 5;
    const int wm = (warp & 3) * 32;
    const int wn = (warp >> 2) * 64;
    const int bh = blockIdx.z;
    const int m0 = blockIdx.y * 128;
    const int n0 = blockIdx.x * 128;

    const __half* q = Q + ((size_t)bh * NN + m0) * DD;
    const __half* k = K + ((size_t)bh * NN + n0) * DD;
#pragma unroll
    for (int rep = 0; rep < 4; ++rep) {
        int idx = t + rep * 256;
        int r = idx >> 3, c8 = idx & 7;
        uint32_t off = sw128(r * 128 + c8 * 16);
        int go = r * DD + c8 * 8;
        cp16(sb + DT_A + off, q + go);
        cp16(sb + DT_B + off, k + go);
    }
    CP_COMMIT();
    asm volatile("cp.async.wait_group 0;" ::: "memory");
    __syncthreads();

    float acc[2][8][4] = {};
#pragma unroll
    for (int ks = 0; ks < 4; ++ks) {
        uint32_t a[2][4];
#pragma unroll
        for (int mt = 0; mt < 2; ++mt) {
            uint32_t row = wm + mt * 16 + (lane & 15);
            uint32_t so = sw128(row * 128 + ks * 32 + (lane >> 4) * 16);
            ldsm4(a[mt], sb + DT_A + so);
        }
        uint32_t bb[4][4];
#pragma unroll
        for (int np = 0; np < 4; ++np) {
            uint32_t row = wn + np * 16 + (lane & 7) + ((lane >> 4) << 3);
            uint32_t so = sw128(row * 128 + ks * 32 + ((lane >> 3) & 1) * 16);
            ldsm4(bb[np], sb + DT_B + so);
        }
#pragma unroll
        for (int mt = 0; mt < 2; ++mt)
#pragma unroll
            for (int nt = 0; nt < 8; ++nt)
                mma16816h(acc[mt][nt], a[mt],
                          bb[nt >> 1][(nt & 1) * 2], bb[nt >> 1][(nt & 1) * 2 + 1]);
    }

    __half* C = Dots + ((size_t)bh * NN + m0) * NN + n0;
#pragma unroll
    for (int mt = 0; mt < 2; ++mt) {
        int row = wm + mt * 16 + (lane >> 2);
#pragma unroll
        for (int nt = 0; nt < 8; ++nt) {
            int col = wn + nt * 8 + (lane & 3) * 2;
            __half2 h0; h0.x = __float2half(acc[mt][nt][0]); h0.y = __float2half(acc[mt][nt][1]);
            __half2 h1; h1.x = __float2half(acc[mt][nt][2]); h1.y = __float2half(acc[mt][nt][3]);
            *(__half2*)(C + (size_t)row * NN + col)       = h0;
            *(__half2*)(C + (size_t)(row + 8) * NN + col) = h1;
        }
    }
}

// ---------------- K3: fused pre-mix + pos + mask + softmax + post-mix --------
__global__ __launch_bounds__(512)
void mix_softmax_kernel(const __half* __restrict__ Dots,
                        const __half* __restrict__ Pos,
                        const unsigned char* __restrict__ Mask,
                        const float* __restrict__ Wpre,
                        const float* __restrict__ Bpre,
                        const float* __restrict__ Wpost,
                        const float* __restrict__ Bpost,
                        __half* __restrict__ Attn)
{
    __shared__ float wpre_s[64], wpost_s[64], bpre_s[8], bpost_s[8];
    __shared__ float red[8][16];
    __shared__ float gstat[8];
    const int b = blockIdx.x;
    const int i = blockIdx.y;
    const int t = threadIdx.x;
    const int lane = t & 31, warp = t >> 5;
    if (t < 64) { wpre_s[t] = Wpre[t]; wpost_s[t] = Wpost[t]; }
    if (t >= 64 && t < 72) { bpre_s[t - 64] = Bpre[t - 64]; bpost_s[t - 64] = Bpost[t - 64]; }
    __syncthreads();

    const int j0 = t * 4;
    float v[4][8];
#pragma unroll
    for (int h = 0; h < 8; ++h) {
        const __half2* src = (const __half2*)(Dots + (((size_t)b * HH + h) * NN + i) * NN + j0);
        __half2 d0 = src[0], d1 = src[1];
        float2 f0 = __half22float2(d0), f1 = __half22float2(d1);
        v[0][h] = f0.x; v[1][h] = f0.y; v[2][h] = f1.x; v[3][h] = f1.y;
    }
#pragma unroll
    for (int c = 0; c < 4; ++c) {
        float sv[8];
#pragma unroll
        for (int h = 0; h < 8; ++h) sv[h] = v[c][h];
#pragma unroll
        for (int g = 0; g < 8; ++g) {
            float val = bpre_s[g];
#pragma unroll
            for (int h = 0; h < 8; ++h) val = fmaf(wpre_s[g * 8 + h], sv[h], val);
            v[c][g] = val;
        }
    }
    uchar4 mk4 = *(const uchar4*)(Mask + ((size_t)b * NN + i) * NN + j0);
    bool mb[4] = {mk4.x != 0, mk4.y != 0, mk4.z != 0, mk4.w != 0};
    float lmax[8];
#pragma unroll
    for (int g = 0; g < 8; ++g) {
        const __half2* psrc = (const __half2*)(Pos + ((size_t)g * NN + i) * NN + j0);
        __half2 q0 = psrc[0], q1 = psrc[1];
        float2 pf0 = __half22float2(q0), pf1 = __half22float2(q1);
        float pa[4] = {pf0.x, pf0.y, pf1.x, pf1.y};
        float m = -FLT_MAX;
#pragma unroll
        for (int c = 0; c < 4; ++c) {
            float val = v[c][g] + pa[c];
            if (mb[c]) val = -FLT_MAX;
            v[c][g] = val;
            m = fmaxf(m, val);
        }
        lmax[g] = m;
    }
#pragma unroll
    for (int g = 0; g < 8; ++g) {
        float m = lmax[g];
#pragma unroll
        for (int o = 16; o > 0; o >>= 1) m = fmaxf(m, __shfl_xor_sync(0xffffffffu, m, o));
        if (lane == 0) red[g][warp] = m;
    }
    __syncthreads();
    if (t < 8) {
        float m = red[t][0];
#pragma unroll
        for (int w = 1; w < 16; ++w) m = fmaxf(m, red[t][w]);
        gstat[t] = m;
    }
    __syncthreads();
    float gmaxr[8];
#pragma unroll
    for (int g = 0; g < 8; ++g) gmaxr[g] = gstat[g];

    float lsum[8] = {};
#pragma unroll
    for (int c = 0; c < 4; ++c)
#pragma unroll
        for (int g = 0; g < 8; ++g) {
            float e = __expf(v[c][g] - gmaxr[g]);
            v[c][g] = e;
            lsum[g] += e;
        }
#pragma unroll
    for (int g = 0; g < 8; ++g) {
        float s = lsum[g];
#pragma unroll
        for (int o = 16; o > 0; o >>= 1) s += __shfl_xor_sync(0xffffffffu, s, o);
        if (lane == 0) red[g][warp] = s;
    }
    __syncthreads();
    if (t < 8) {
        float s = 0.f;
#pragma unroll
        for (int w = 0; w < 16; ++w) s += red[t][w];
        gstat[t] = 1.0f / s;
    }
    __syncthreads();
#pragma unroll
    for (int h = 0; h < 8; ++h) {
        float inv = gstat[h];
#pragma unroll
        for (int c = 0; c < 4; ++c) v[c][h] *= inv;
    }
#pragma unroll
    for (int g = 0; g < 8; ++g) {
        float o[4];
#pragma unroll
        for (int c = 0; c < 4; ++c) {
            float acc = bpost_s[g];
#pragma unroll
            for (int h = 0; h < 8; ++h) acc = fmaf(wpost_s[g * 8 + h], v[c][h], acc);
            o[c] = acc;
        }
        size_t ofs = (((size_t)b * HH + g) * NN + i) * NN + j0;
        __half2 p0; p0.x = __float2half(o[0]); p0.y = __float2half(o[1]);
        __half2 p1; p1.x = __float2half(o[2]); p1.y = __float2half(o[3]);
        *(__half2*)(Attn + ofs)     = p0;
        *(__half2*)(Attn + ofs + 2) = p1;
    }
}

// ---------------- K4: out = attn(f16) @ v(f16 single), 1 combo ----------------
#define AVF_A  0
#define AVF_B  16384
#define AVF_STRIDE 24576
#define AVF_SMEM (3 * AVF_STRIDE)

__device__ __forceinline__ void av_load_stage(uint32_t st,
    const __half* __restrict__ A, const __half* __restrict__ V, int j0)
{
    const int t = threadIdx.x;
#pragma unroll
    for (int rep = 0; rep < 4; ++rep) {
        int idx = t + rep * 256;
        int r = idx >> 3, c8 = idx & 7;
        uint32_t off = sw128(r * 128 + c8 * 16);
        cp16(st + AVF_A + off, A + (size_t)r * NN + j0 + c8 * 8);
    }
#pragma unroll
    for (int rep = 0; rep < 2; ++rep) {
        int idx = t + rep * 256;
        int r = idx >> 3, c8 = idx & 7;
        uint32_t off = sw128(r * 128 + c8 * 16);
        cp16(st + AVF_B + off, V + (size_t)r * NN + j0 + c8 * 8);
    }
}

__global__ __launch_bounds__(256, 2)
void av_mma_kernel(const __half* __restrict__ Attn, const __half* __restrict__ VT,
                   __nv_bfloat16* __restrict__ OutH, __nv_bfloat16* __restrict__ OutL)
{
    extern __shared__ __align__(128) char smem[];
    const uint32_t sb = smem_u32(smem);
    const int lane = threadIdx.x & 31, warp = threadIdx.x >> 5;
    const int wm = (warp & 3) * 32, wn = (warp >> 2) * 32;
    const int bh = blockIdx.y;
    const int b = bh >> 3, h = bh & 7;
    const int m0 = blockIdx.x * 128;

    const __half* A = Attn + ((size_t)bh * NN + m0) * NN;
    const __half* V = VT + (size_t)bh * DD * NN;

    float acc[2][4][4] = {};
    const int nk = 32;
    av_load_stage(sb, A, V, 0); CP_COMMIT();
    av_load_stage(sb + AVF_STRIDE, A, V, 64); CP_COMMIT();

    for (int kc = 0; kc < nk; ++kc) {
        if (kc + 2 < nk) {
            av_load_stage(sb + ((kc + 2) % 3) * AVF_STRIDE, A, V, (kc + 2) * 64);
            CP_COMMIT();
        }
        int pend = (nk < kc + 3 ? nk : kc + 3) - (kc + 1);
        cp_wait_dyn(pend);
        __syncthreads();
        const uint32_t st = sb + (kc % 3) * AVF_STRIDE;
#pragma unroll
        for (int ks = 0; ks < 4; ++ks) {
            uint32_t a[2][4];
#pragma unroll
            for (int mt = 0; mt < 2; ++mt) {
                uint32_t row = wm + mt * 16 + (lane & 15);
                uint32_t so = sw128(row * 128 + ks * 32 + (lane >> 4) * 16);
                ldsm4(a[mt], st + AVF_A + so);
            }
            uint32_t bb[2][4];
#pragma unroll
            for (int np = 0; np < 2; ++np) {
                uint32_t row = wn + np * 16 + (lane & 7) + ((lane >> 4) << 3);
                uint32_t so = sw128(row * 128 + ks * 32 + ((lane >> 3) & 1) * 16);
                ldsm4(bb[np], st + AVF_B + so);
            }
#pragma unroll
            for (int mt = 0; mt < 2; ++mt)
#pragma unroll
                for (int nt = 0; nt < 4; ++nt)
                    mma16816h(acc[mt][nt], a[mt],
                              bb[nt >> 1][(nt & 1) * 2], bb[nt >> 1][(nt & 1) * 2 + 1]);
        }
        __syncthreads();
    }

#pragma unroll
    for (int mt = 0; mt < 2; ++mt) {
        int row = m0 + wm + mt * 16 + (lane >> 2);
#pragma unroll
        for (int half = 0; half < 2; ++half) {
            size_t rb = ((size_t)b * NN + row + half * 8) * (HH * DD) + h * DD;
#pragma unroll
            for (int nt = 0; nt < 4; ++nt) {
                int col = wn + nt * 8 + (lane & 3) * 2;
                float v0 = acc[mt][nt][half * 2 + 0];
                float v1 = acc[mt][nt][half * 2 + 1];
                __nv_bfloat16 h0 = __float2bfloat16(v0);
                __nv_bfloat16 h1 = __float2bfloat16(v1);
                __nv_bfloat162 hp; hp.x = h0; hp.y = h1;
                __nv_bfloat162 lp;
                lp.x = __float2bfloat16(v0 - __bfloat162float(h0));
                lp.y = __float2bfloat16(v1 - __bfloat162float(h1));
                *(__nv_bfloat162*)(OutH + rb + col) = hp;
                *(__nv_bfloat162*)(OutL + rb + col) = lp;
            }
        }
    }
}

// ---------------- K5: final projection y = outf @ Wout^T ---------------------
__global__ __launch_bounds__(256, 2)
void out_mma_kernel(const __nv_bfloat16* __restrict__ OH, const __nv_bfloat16* __restrict__ OL,
                    const __nv_bfloat16* __restrict__ WH, const __nv_bfloat16* __restrict__ WL,
                    float* __restrict__ Y)
{
    extern __shared__ __align__(128) char smem[];
    const uint32_t sb = smem_u32(smem);
    const int m0 = blockIdx.y * 128;
    const int n0 = blockIdx.x * 64;
    const int lane = threadIdx.x & 31, warp = threadIdx.x >> 5;
    const int wm = (warp & 3) * 32, wn = (warp >> 2) * 32;
    float acc[2][4][4] = {};
    mma_pipeline(OH, OL, HH * DD, m0, WH, WL, HH * DD, n0, HH * DD, sb, acc, lane, wm, wn);

#pragma unroll
    for (int mt = 0; mt < 2; ++mt) {
        int row = m0 + wm + mt * 16 + (lane >> 2);
#pragma unroll
        for (int nt = 0; nt < 4; ++nt) {
            int col = n0 + wn + nt * 8 + (lane & 3) * 2;
            *(float2*)(Y + (size_t)row * CC + col)       = make_float2(acc[mt][nt][0], acc[mt][nt][1]);
            *(float2*)(Y + (size_t)(row + 8) * CC + col) = make_float2(acc[mt][nt][2], acc[mt][nt][3]);
        }
    }
}

// ---------------- launch -----------------------------------------------------
extern "C" void kernel_launch(void* const* d_in, const int* in_sizes, int n_in,
                              void* d_out, int out_size)
{
    (void)in_sizes; (void)n_in; (void)out_size;
    const float*         x     = (const float*)d_in[0];
    const float*         pos   = (const float*)d_in[1];
    const unsigned char* mask  = (const unsigned char*)d_in[2];
    const float*         Wqkv  = (const float*)d_in[3];
    const float*         Wout  = (const float*)d_in[4];
    const float*         Wpre  = (const float*)d_in[5];
    const float*         bpre  = (const float*)d_in[6];
    const float*         Wpost = (const float*)d_in[7];
    const float*         bpost = (const float*)d_in[8];
    float* y = (float*)d_out;

    float *v;
    __half *dots, *q, *k, *posh;
    __nv_bfloat16 *xh, *xl, *wqh, *wql, *woh, *wol;
    __nv_bfloat16 *oh, *ol;
    __half *vt, *attn;
    cudaGetSymbolAddress((void**)&v,    g_v);
    cudaGetSymbolAddress((void**)&dots, g_dots);
    cudaGetSymbolAddress((void**)&xh,  g_xh);
    cudaGetSymbolAddress((void**)&xl,  g_xl);
    cudaGetSymbolAddress((void**)&wqh, g_wqh);
    cudaGetSymbolAddress((void**)&wql, g_wql);
    cudaGetSymbolAddress((void**)&woh, g_woh);
    cudaGetSymbolAddress((void**)&wol, g_wol);
    cudaGetSymbolAddress((void**)&q,   g_qs);
    cudaGetSymbolAddress((void**)&k,   g_ks);
    cudaGetSymbolAddress((void**)&posh, g_posh);
    cudaGetSymbolAddress((void**)&vt,  g_vt);
    cudaGetSymbolAddress((void**)&attn, g_attn);
    cudaGetSymbolAddress((void**)&oh,  g_outf_hi);
    cudaGetSymbolAddress((void**)&ol,  g_outf_lo);

    cudaFuncSetAttribute(qkv_mma_kernel,  cudaFuncAttributeMaxDynamicSharedMemorySize, PIPE_SMEM);
    cudaFuncSetAttribute(out_mma_kernel,  cudaFuncAttributeMaxDynamicSharedMemorySize, PIPE_SMEM);
    cudaFuncSetAttribute(dots_mma_kernel, cudaFuncAttributeMaxDynamicSharedMemorySize, DK_SMEM);
    cudaFuncSetAttribute(av_mma_kernel,   cudaFuncAttributeMaxDynamicSharedMemorySize, AVF_SMEM);

    split_kernel<<<(BB * NN * CC + 255) / 256, 256>>>(x, xh, xl, BB * NN * CC);
    split_wqkv_kernel<<<(FF * CC + 255) / 256, 256>>>(Wqkv, wqh, wql);
    split_kernel<<<(CC * HH * DD + 255) / 256, 256>>>(Wout, woh, wol, CC * HH * DD);
    convert_pos_kernel<<<(HH * NN * NN + 255) / 256, 256>>>(pos, posh, HH * NN * NN);

    qkv_mma_kernel<<<dim3(FF / 64, (BB * NN) / 128), 256, PIPE_SMEM>>>(xh, xl, wqh, wql, q, k, v);
    convert_v_kernel<<<dim3(NN / 64, BB * HH), 256>>>(v, vt);
    dots_mma_kernel<<<dim3(NN / 128, NN / 128, BB * HH), 256, DK_SMEM>>>(q, k, dots);
    mix_softmax_kernel<<<dim3(BB, NN), 512>>>(dots, posh, mask, Wpre, bpre, Wpost, bpost, attn);
    av_mma_kernel<<<dim3(NN / 128, BB * HH), 256, AVF_SMEM>>>(attn, vt, oh, ol);
    out_mma_kernel<<<dim3(CC / 64, (BB * NN) / 128), 256, PIPE_SMEM>>>(oh, ol, woh, wol, y);
}

// round 16
// speedup vs baseline: 1.6743x; 1.6743x over previous
#include <cuda_runtime.h>
#include <cuda_bf16.h>
#include <cuda_fp16.h>
#include <math.h>
#include <float.h>
#include <stdint.h>

// Problem constants
#define BB 2
#define NN 2048
#define CC 512
#define HH 8
#define DD 64
#define FF 1536   // 3*H*D

// ==================== scratch (device globals) ====================
__device__ float g_v[BB * HH * NN * DD];
__device__ __align__(256) __half g_dots[(size_t)BB * HH * NN * NN];   // 128 MiB fp16
__device__ __align__(256) __nv_bfloat16 g_xh[BB * NN * CC];
__device__ __align__(256) __nv_bfloat16 g_xl[BB * NN * CC];
__device__ __align__(256) __nv_bfloat16 g_wqh[FF * CC];        // permuted f' = s*512+h*64+d
__device__ __align__(256) __nv_bfloat16 g_wql[FF * CC];
__device__ __align__(256) __nv_bfloat16 g_woh[CC * HH * DD];
__device__ __align__(256) __nv_bfloat16 g_wol[CC * HH * DD];
__device__ __align__(256) __half g_qs[BB * HH * NN * DD];      // fp16 single (scale folded)
__device__ __align__(256) __half g_ks[BB * HH * NN * DD];      // fp16 single
__device__ __align__(256) __half g_vt[BB * HH * DD * NN];      // [bh][d][n] fp16 single
__device__ __align__(256) __half g_attn[(size_t)BB * HH * NN * NN];   // 128 MiB fp16 single
__device__ __align__(256) __nv_bfloat16 g_outf_hi[BB * NN * (HH * DD)];
__device__ __align__(256) __nv_bfloat16 g_outf_lo[BB * NN * (HH * DD)];

// ==================== helpers ====================
__device__ __forceinline__ uint32_t smem_u32(const void* p) {
    uint32_t a;
    asm("{ .reg .u64 t; cvta.to.shared.u64 t, %1; cvt.u32.u64 %0, t; }" : "=r"(a) : "l"(p));
    return a;
}
__device__ __forceinline__ uint32_t sw64(uint32_t off)  { return off ^ ((off >> 3) & 0x30); }
__device__ __forceinline__ uint32_t sw128(uint32_t off) { return off ^ ((off >> 3) & 0x70); }

__device__ __forceinline__ void ldsm4(uint32_t (&r)[4], uint32_t addr) {
    asm volatile("ldmatrix.sync.aligned.m8n8.x4.shared.b16 {%0,%1,%2,%3}, [%4];"
        : "=r"(r[0]), "=r"(r[1]), "=r"(r[2]), "=r"(r[3]) : "r"(addr));
}
__device__ __forceinline__ void mma16816(float (&c)[4], const uint32_t (&a)[4],
                                         uint32_t b0, uint32_t b1) {
    asm volatile("mma.sync.aligned.m16n8k16.row.col.f32.bf16.bf16.f32 "
        "{%0,%1,%2,%3}, {%4,%5,%6,%7}, {%8,%9}, {%0,%1,%2,%3};"
        : "+f"(c[0]), "+f"(c[1]), "+f"(c[2]), "+f"(c[3])
        : "r"(a[0]), "r"(a[1]), "r"(a[2]), "r"(a[3]), "r"(b0), "r"(b1));
}
__device__ __forceinline__ void mma16816h(float (&c)[4], const uint32_t (&a)[4],
                                          uint32_t b0, uint32_t b1) {
    asm volatile("mma.sync.aligned.m16n8k16.row.col.f32.f16.f16.f32 "
        "{%0,%1,%2,%3}, {%4,%5,%6,%7}, {%8,%9}, {%0,%1,%2,%3};"
        : "+f"(c[0]), "+f"(c[1]), "+f"(c[2]), "+f"(c[3])
        : "r"(a[0]), "r"(a[1]), "r"(a[2]), "r"(a[3]), "r"(b0), "r"(b1));
}
__device__ __forceinline__ void cp16(uint32_t saddr, const void* gptr) {
    asm volatile("cp.async.cg.shared.global [%0], [%1], 16;" :: "r"(saddr), "l"(gptr));
}
#define CP_COMMIT() asm volatile("cp.async.commit_group;" ::: "memory")
__device__ __forceinline__ void cp_wait_dyn(int pend) {
    if (pend >= 2)      asm volatile("cp.async.wait_group 2;" ::: "memory");
    else if (pend == 1) asm volatile("cp.async.wait_group 1;" ::: "memory");
    else                asm volatile("cp.async.wait_group 0;" ::: "memory");
}

// ==================== bf16 pipelined core (CTA 128x64, Kc=32, SW64) ===========
#define SA_H 0
#define SA_L 8192
#define SB_H 16384
#define SB_L 20480
#define ST_STRIDE 24576
#define PIPE_SMEM (3 * ST_STRIDE)

__device__ __forceinline__ void load_stage(
    uint32_t st, const __nv_bfloat16* __restrict__ AH, const __nv_bfloat16* __restrict__ AL,
    int lda, int m0, const __nv_bfloat16* __restrict__ BH, const __nv_bfloat16* __restrict__ BL,
    int ldb, int n0, int k0)
{
    const int t = threadIdx.x;
#pragma unroll
    for (int rep = 0; rep < 2; ++rep) {
        int idx = t + rep * 256;
        int r = idx >> 2, c4 = idx & 3;
        uint32_t off = sw64(r * 64 + c4 * 16);
        size_t ga = (size_t)(m0 + r) * lda + k0 + c4 * 8;
        cp16(st + SA_H + off, AH + ga);
        cp16(st + SA_L + off, AL + ga);
    }
    {
        int r = t >> 2, c4 = t & 3;
        uint32_t off = sw64(r * 64 + c4 * 16);
        size_t gb = (size_t)(n0 + r) * ldb + k0 + c4 * 8;
        cp16(st + SB_H + off, BH + gb);
        cp16(st + SB_L + off, BL + gb);
    }
}

__device__ __forceinline__ void compute_stage(uint32_t st, float (&acc)[2][4][4],
                                              int lane, int wm, int wn)
{
#pragma unroll
    for (int ks = 0; ks < 2; ++ks) {
        uint32_t aH[2][4], aL[2][4];
#pragma unroll
        for (int mt = 0; mt < 2; ++mt) {
            uint32_t row = wm + mt * 16 + (lane & 15);
            uint32_t so = sw64(row * 64 + ks * 32 + (lane >> 4) * 16);
            ldsm4(aH[mt], st + SA_H + so);
            ldsm4(aL[mt], st + SA_L + so);
        }
        uint32_t bH[2][4], bL[2][4];
#pragma unroll
        for (int np = 0; np < 2; ++np) {
            uint32_t row = wn + np * 16 + (lane & 7) + ((lane >> 4) << 3);
            uint32_t so = sw64(row * 64 + ks * 32 + ((lane >> 3) & 1) * 16);
            ldsm4(bH[np], st + SB_H + so);
            ldsm4(bL[np], st + SB_L + so);
        }
#pragma unroll
        for (int mt = 0; mt < 2; ++mt)
#pragma unroll
            for (int nt = 0; nt < 4; ++nt) {
                uint32_t b0h = bH[nt >> 1][(nt & 1) * 2], b1h = bH[nt >> 1][(nt & 1) * 2 + 1];
                uint32_t b0l = bL[nt >> 1][(nt & 1) * 2], b1l = bL[nt >> 1][(nt & 1) * 2 + 1];
                mma16816(acc[mt][nt], aH[mt], b0h, b1h);
                mma16816(acc[mt][nt], aH[mt], b0l, b1l);
                mma16816(acc[mt][nt], aL[mt], b0h, b1h);
            }
    }
}

__device__ __forceinline__ void mma_pipeline(
    const __nv_bfloat16* __restrict__ AH, const __nv_bfloat16* __restrict__ AL, int lda, int m0,
    const __nv_bfloat16* __restrict__ BH, const __nv_bfloat16* __restrict__ BL, int ldb, int n0,
    int K, uint32_t sb, float (&acc)[2][4][4], int lane, int wm, int wn)
{
    const int nk = K / 32;
    load_stage(sb, AH, AL, lda, m0, BH, BL, ldb, n0, 0);
    CP_COMMIT();
    if (nk > 1) {
        load_stage(sb + ST_STRIDE, AH, AL, lda, m0, BH, BL, ldb, n0, 32);
        CP_COMMIT();
    }
    for (int kc = 0; kc < nk; ++kc) {
        if (kc + 2 < nk) {
            load_stage(sb + ((kc + 2) % 3) * ST_STRIDE, AH, AL, lda, m0, BH, BL, ldb, n0,
                       (kc + 2) * 32);
            CP_COMMIT();
        }
        int pend = (nk < kc + 3 ? nk : kc + 3) - (kc + 1);
        cp_wait_dyn(pend);
        __syncthreads();
        compute_stage(sb + (kc % 3) * ST_STRIDE, acc, lane, wm, wn);
        __syncthreads();
    }
}

// ---------------- K0a: plain split fp32 -> bf16 hi/lo ----------------
__global__ void split_kernel(const float* __restrict__ in, __nv_bfloat16* __restrict__ hi,
                             __nv_bfloat16* __restrict__ lo, int n)
{
    int i = blockIdx.x * 256 + threadIdx.x;
    if (i < n) {
        float v = in[i];
        __nv_bfloat16 h = __float2bfloat16(v);
        hi[i] = h;
        lo[i] = __float2bfloat16(v - __bfloat162float(h));
    }
}

// ---------------- K0b: permuted+scaled split of Wqkv ----------------
__global__ void split_wqkv_kernel(const float* __restrict__ W,
                                  __nv_bfloat16* __restrict__ hi, __nv_bfloat16* __restrict__ lo)
{
    int i = blockIdx.x * 256 + threadIdx.x;
    if (i < FF * CC) {
        int f = i >> 9;
        int c = i & 511;
        int h = f / 192;
        int r = f - h * 192;
        int d = r / 3;
        int s = r - d * 3;
        int fp = s * 512 + h * 64 + d;
        float v = W[i] * (s == 0 ? 0.125f : 1.0f);
        __nv_bfloat16 hb = __float2bfloat16(v);
        hi[fp * 512 + c] = hb;
        lo[fp * 512 + c] = __float2bfloat16(v - __bfloat162float(hb));
    }
}

// ---------------- K1: QKV projection + coalesced scatter ----------------
__global__ __launch_bounds__(256, 2)
void qkv_mma_kernel(const __nv_bfloat16* __restrict__ XH, const __nv_bfloat16* __restrict__ XL,
                    const __nv_bfloat16* __restrict__ WH, const __nv_bfloat16* __restrict__ WL,
                    __half* __restrict__ Q, __half* __restrict__ K,
                    float* __restrict__ V)
{
    extern __shared__ __align__(128) char smem[];
    const uint32_t sb = smem_u32(smem);
    const int m0 = blockIdx.y * 128;
    const int n0 = blockIdx.x * 64;
    const int s = n0 >> 9;
    const int h = (n0 >> 6) & 7;
    const int lane = threadIdx.x & 31, warp = threadIdx.x >> 5;
    const int wm = (warp & 3) * 32, wn = (warp >> 2) * 32;
    float acc[2][4][4] = {};
    mma_pipeline(XH, XL, CC, m0, WH, WL, CC, n0, CC, sb, acc, lane, wm, wn);

#pragma unroll
    for (int mt = 0; mt < 2; ++mt) {
#pragma unroll
        for (int half = 0; half < 2; ++half) {
            int m = m0 + wm + mt * 16 + (lane >> 2) + half * 8;
            int b = m >> 11, n = m & 2047;
            size_t base = (((size_t)b * HH + h) * NN + n) * DD;
#pragma unroll
            for (int nt = 0; nt < 4; ++nt) {
                int d = wn + nt * 8 + (lane & 3) * 2;
                float v0 = acc[mt][nt][half * 2 + 0];
                float v1 = acc[mt][nt][half * 2 + 1];
                if (s == 2) {
                    *(float2*)(V + base + d) = make_float2(v0, v1);
                } else {
                    __half2 hp; hp.x = __float2half(v0); hp.y = __float2half(v1);
                    if (s == 0) *(__half2*)(Q + base + d) = hp;
                    else        *(__half2*)(K + base + d) = hp;
                }
            }
        }
    }
}

// ---------------- K1b: transpose V -> vt (fp16 single) -----------------------
__global__ void convert_v_kernel(const float* __restrict__ V, __half* __restrict__ VT)
{
    __shared__ float ts[64][65];
    const int bh = blockIdx.y;
    const int n0 = blockIdx.x * 64;
    const int t = threadIdx.x;
    const size_t base = ((size_t)bh * NN + n0) * DD;
    for (int idx = t; idx < 64 * 64; idx += 256)
        ts[idx >> 6][idx & 63] = V[base + idx];
    __syncthreads();
    for (int idx = t; idx < 64 * 64; idx += 256) {
        int d = idx >> 6, c = idx & 63;
        VT[((size_t)bh * DD + d) * NN + n0 + c] = __float2half(ts[c][d]);
    }
}

// ---------------- K2: dots = q(f16) @ k(f16)^T, 1 combo ----------------------
#define DT_A 0
#define DT_B 16384
#define DK_SMEM 32768

__global__ __launch_bounds__(256, 2)
void dots_mma_kernel(const __half* __restrict__ Q, const __half* __restrict__ K,
                     __half* __restrict__ Dots)
{
    extern __shared__ __align__(128) char smem[];
    const uint32_t sb = smem_u32(smem);
    const int t = threadIdx.x;
    const int lane = t & 31, warp = t >> 5;
    const int wm = (warp & 3) * 32;
    const int wn = (warp >> 2) * 64;
    const int bh = blockIdx.z;
    const int m0 = blockIdx.y * 128;
    const int n0 = blockIdx.x * 128;

    const __half* q = Q + ((size_t)bh * NN + m0) * DD;
    const __half* k = K + ((size_t)bh * NN + n0) * DD;
#pragma unroll
    for (int rep = 0; rep < 4; ++rep) {
        int idx = t + rep * 256;
        int r = idx >> 3, c8 = idx & 7;
        uint32_t off = sw128(r * 128 + c8 * 16);
        int go = r * DD + c8 * 8;
        cp16(sb + DT_A + off, q + go);
        cp16(sb + DT_B + off, k + go);
    }
    CP_COMMIT();
    asm volatile("cp.async.wait_group 0;" ::: "memory");
    __syncthreads();

    float acc[2][8][4] = {};
#pragma unroll
    for (int ks = 0; ks < 4; ++ks) {
        uint32_t a[2][4];
#pragma unroll
        for (int mt = 0; mt < 2; ++mt) {
            uint32_t row = wm + mt * 16 + (lane & 15);
            uint32_t so = sw128(row * 128 + ks * 32 + (lane >> 4) * 16);
            ldsm4(a[mt], sb + DT_A + so);
        }
        uint32_t bb[4][4];
#pragma unroll
        for (int np = 0; np < 4; ++np) {
            uint32_t row = wn + np * 16 + (lane & 7) + ((lane >> 4) << 3);
            uint32_t so = sw128(row * 128 + ks * 32 + ((lane >> 3) & 1) * 16);
            ldsm4(bb[np], sb + DT_B + so);
        }
#pragma unroll
        for (int mt = 0; mt < 2; ++mt)
#pragma unroll
            for (int nt = 0; nt < 8; ++nt)
                mma16816h(acc[mt][nt], a[mt],
                          bb[nt >> 1][(nt & 1) * 2], bb[nt >> 1][(nt & 1) * 2 + 1]);
    }

    __half* C = Dots + ((size_t)bh * NN + m0) * NN + n0;
#pragma unroll
    for (int mt = 0; mt < 2; ++mt) {
        int row = wm + mt * 16 + (lane >> 2);
#pragma unroll
        for (int nt = 0; nt < 8; ++nt) {
            int col = wn + nt * 8 + (lane & 3) * 2;
            __half2 h0; h0.x = __float2half(acc[mt][nt][0]); h0.y = __float2half(acc[mt][nt][1]);
            __half2 h1; h1.x = __float2half(acc[mt][nt][2]); h1.y = __float2half(acc[mt][nt][3]);
            *(__half2*)(C + (size_t)row * NN + col)       = h0;
            *(__half2*)(C + (size_t)(row + 8) * NN + col) = h1;
        }
    }
}

// ---------------- K3: fused pre-mix + pos(fp32) + mask + softmax + post-mix ---
__global__ __launch_bounds__(512)
void mix_softmax_kernel(const __half* __restrict__ Dots,
                        const float* __restrict__ Pos,
                        const unsigned char* __restrict__ Mask,
                        const float* __restrict__ Wpre,
                        const float* __restrict__ Bpre,
                        const float* __restrict__ Wpost,
                        const float* __restrict__ Bpost,
                        __half* __restrict__ Attn)
{
    __shared__ float wpre_s[64], wpost_s[64], bpre_s[8], bpost_s[8];
    __shared__ float red[8][16];
    __shared__ float gstat[8];
    const int b = blockIdx.x;
    const int i = blockIdx.y;
    const int t = threadIdx.x;
    const int lane = t & 31, warp = t >> 5;
    if (t < 64) { wpre_s[t] = Wpre[t]; wpost_s[t] = Wpost[t]; }
    if (t >= 64 && t < 72) { bpre_s[t - 64] = Bpre[t - 64]; bpost_s[t - 64] = Bpost[t - 64]; }
    __syncthreads();

    const int j0 = t * 4;
    float v[4][8];
#pragma unroll
    for (int h = 0; h < 8; ++h) {
        const __half2* src = (const __half2*)(Dots + (((size_t)b * HH + h) * NN + i) * NN + j0);
        __half2 d0 = src[0], d1 = src[1];
        float2 f0 = __half22float2(d0), f1 = __half22float2(d1);
        v[0][h] = f0.x; v[1][h] = f0.y; v[2][h] = f1.x; v[3][h] = f1.y;
    }
#pragma unroll
    for (int c = 0; c < 4; ++c) {
        float sv[8];
#pragma unroll
        for (int h = 0; h < 8; ++h) sv[h] = v[c][h];
#pragma unroll
        for (int g = 0; g < 8; ++g) {
            float val = bpre_s[g];
#pragma unroll
            for (int h = 0; h < 8; ++h) val = fmaf(wpre_s[g * 8 + h], sv[h], val);
            v[c][g] = val;
        }
    }
    uchar4 mk4 = *(const uchar4*)(Mask + ((size_t)b * NN + i) * NN + j0);
    bool mb[4] = {mk4.x != 0, mk4.y != 0, mk4.z != 0, mk4.w != 0};
    float lmax[8];
#pragma unroll
    for (int g = 0; g < 8; ++g) {
        float4 p4 = *(const float4*)(Pos + ((size_t)g * NN + i) * NN + j0);
        float pa[4] = {p4.x, p4.y, p4.z, p4.w};
        float m = -FLT_MAX;
#pragma unroll
        for (int c = 0; c < 4; ++c) {
            float val = v[c][g] + pa[c];
            if (mb[c]) val = -FLT_MAX;
            v[c][g] = val;
            m = fmaxf(m, val);
        }
        lmax[g] = m;
    }
#pragma unroll
    for (int g = 0; g < 8; ++g) {
        float m = lmax[g];
#pragma unroll
        for (int o = 16; o > 0; o >>= 1) m = fmaxf(m, __shfl_xor_sync(0xffffffffu, m, o));
        if (lane == 0) red[g][warp] = m;
    }
    __syncthreads();
    if (t < 8) {
        float m = red[t][0];
#pragma unroll
        for (int w = 1; w < 16; ++w) m = fmaxf(m, red[t][w]);
        gstat[t] = m;
    }
    __syncthreads();
    float gmaxr[8];
#pragma unroll
    for (int g = 0; g < 8; ++g) gmaxr[g] = gstat[g];

    float lsum[8] = {};
#pragma unroll
    for (int c = 0; c < 4; ++c)
#pragma unroll
        for (int g = 0; g < 8; ++g) {
            float e = __expf(v[c][g] - gmaxr[g]);
            v[c][g] = e;
            lsum[g] += e;
        }
#pragma unroll
    for (int g = 0; g < 8; ++g) {
        float s = lsum[g];
#pragma unroll
        for (int o = 16; o > 0; o >>= 1) s += __shfl_xor_sync(0xffffffffu, s, o);
        if (lane == 0) red[g][warp] = s;
    }
    __syncthreads();
    if (t < 8) {
        float s = 0.f;
#pragma unroll
        for (int w = 0; w < 16; ++w) s += red[t][w];
        gstat[t] = 1.0f / s;
    }
    __syncthreads();
#pragma unroll
    for (int h = 0; h < 8; ++h) {
        float inv = gstat[h];
#pragma unroll
        for (int c = 0; c < 4; ++c) v[c][h] *= inv;
    }
#pragma unroll
    for (int g = 0; g < 8; ++g) {
        float o[4];
#pragma unroll
        for (int c = 0; c < 4; ++c) {
            float acc = bpost_s[g];
#pragma unroll
            for (int h = 0; h < 8; ++h) acc = fmaf(wpost_s[g * 8 + h], v[c][h], acc);
            o[c] = acc;
        }
        size_t ofs = (((size_t)b * HH + g) * NN + i) * NN + j0;
        __half2 p0; p0.x = __float2half(o[0]); p0.y = __float2half(o[1]);
        __half2 p1; p1.x = __float2half(o[2]); p1.y = __float2half(o[3]);
        *(__half2*)(Attn + ofs)     = p0;
        *(__half2*)(Attn + ofs + 2) = p1;
    }
}

// ---------------- K4: out = attn(f16) @ v(f16 single), 1 combo ----------------
#define AVF_A  0
#define AVF_B  16384
#define AVF_STRIDE 24576
#define AVF_SMEM (3 * AVF_STRIDE)

__device__ __forceinline__ void av_load_stage(uint32_t st,
    const __half* __restrict__ A, const __half* __restrict__ V, int j0)
{
    const int t = threadIdx.x;
#pragma unroll
    for (int rep = 0; rep < 4; ++rep) {
        int idx = t + rep * 256;
        int r = idx >> 3, c8 = idx & 7;
        uint32_t off = sw128(r * 128 + c8 * 16);
        cp16(st + AVF_A + off, A + (size_t)r * NN + j0 + c8 * 8);
    }
#pragma unroll
    for (int rep = 0; rep < 2; ++rep) {
        int idx = t + rep * 256;
        int r = idx >> 3, c8 = idx & 7;
        uint32_t off = sw128(r * 128 + c8 * 16);
        cp16(st + AVF_B + off, V + (size_t)r * NN + j0 + c8 * 8);
    }
}

__global__ __launch_bounds__(256, 2)
void av_mma_kernel(const __half* __restrict__ Attn, const __half* __restrict__ VT,
                   __nv_bfloat16* __restrict__ OutH, __nv_bfloat16* __restrict__ OutL)
{
    extern __shared__ __align__(128) char smem[];
    const uint32_t sb = smem_u32(smem);
    const int lane = threadIdx.x & 31, warp = threadIdx.x >> 5;
    const int wm = (warp & 3) * 32, wn = (warp >> 2) * 32;
    const int bh = blockIdx.y;
    const int b = bh >> 3, h = bh & 7;
    const int m0 = blockIdx.x * 128;

    const __half* A = Attn + ((size_t)bh * NN + m0) * NN;
    const __half* V = VT + (size_t)bh * DD * NN;

    float acc[2][4][4] = {};
    const int nk = 32;
    av_load_stage(sb, A, V, 0); CP_COMMIT();
    av_load_stage(sb + AVF_STRIDE, A, V, 64); CP_COMMIT();

    for (int kc = 0; kc < nk; ++kc) {
        if (kc + 2 < nk) {
            av_load_stage(sb + ((kc + 2) % 3) * AVF_STRIDE, A, V, (kc + 2) * 64);
            CP_COMMIT();
        }
        int pend = (nk < kc + 3 ? nk : kc + 3) - (kc + 1);
        cp_wait_dyn(pend);
        __syncthreads();
        const uint32_t st = sb + (kc % 3) * AVF_STRIDE;
#pragma unroll
        for (int ks = 0; ks < 4; ++ks) {
            uint32_t a[2][4];
#pragma unroll
            for (int mt = 0; mt < 2; ++mt) {
                uint32_t row = wm + mt * 16 + (lane & 15);
                uint32_t so = sw128(row * 128 + ks * 32 + (lane >> 4) * 16);
                ldsm4(a[mt], st + AVF_A + so);
            }
            uint32_t bb[2][4];
#pragma unroll
            for (int np = 0; np < 2; ++np) {
                uint32_t row = wn + np * 16 + (lane & 7) + ((lane >> 4) << 3);
                uint32_t so = sw128(row * 128 + ks * 32 + ((lane >> 3) & 1) * 16);
                ldsm4(bb[np], st + AVF_B + so);
            }
#pragma unroll
            for (int mt = 0; mt < 2; ++mt)
#pragma unroll
                for (int nt = 0; nt < 4; ++nt)
                    mma16816h(acc[mt][nt], a[mt],
                              bb[nt >> 1][(nt & 1) * 2], bb[nt >> 1][(nt & 1) * 2 + 1]);
        }
        __syncthreads();
    }

#pragma unroll
    for (int mt = 0; mt < 2; ++mt) {
        int row = m0 + wm + mt * 16 + (lane >> 2);
#pragma unroll
        for (int half = 0; half < 2; ++half) {
            size_t rb = ((size_t)b * NN + row + half * 8) * (HH * DD) + h * DD;
#pragma unroll
            for (int nt = 0; nt < 4; ++nt) {
                int col = wn + nt * 8 + (lane & 3) * 2;
                float v0 = acc[mt][nt][half * 2 + 0];
                float v1 = acc[mt][nt][half * 2 + 1];
                __nv_bfloat16 h0 = __float2bfloat16(v0);
                __nv_bfloat16 h1 = __float2bfloat16(v1);
                __nv_bfloat162 hp; hp.x = h0; hp.y = h1;
                __nv_bfloat162 lp;
                lp.x = __float2bfloat16(v0 - __bfloat162float(h0));
                lp.y = __float2bfloat16(v1 - __bfloat162float(h1));
                *(__nv_bfloat162*)(OutH + rb + col) = hp;
                *(__nv_bfloat162*)(OutL + rb + col) = lp;
            }
        }
    }
}

// ---------------- K5: final projection y = outf @ Wout^T ---------------------
__global__ __launch_bounds__(256, 2)
void out_mma_kernel(const __nv_bfloat16* __restrict__ OH, const __nv_bfloat16* __restrict__ OL,
                    const __nv_bfloat16* __restrict__ WH, const __nv_bfloat16* __restrict__ WL,
                    float* __restrict__ Y)
{
    extern __shared__ __align__(128) char smem[];
    const uint32_t sb = smem_u32(smem);
    const int m0 = blockIdx.y * 128;
    const int n0 = blockIdx.x * 64;
    const int lane = threadIdx.x & 31, warp = threadIdx.x >> 5;
    const int wm = (warp & 3) * 32, wn = (warp >> 2) * 32;
    float acc[2][4][4] = {};
    mma_pipeline(OH, OL, HH * DD, m0, WH, WL, HH * DD, n0, HH * DD, sb, acc, lane, wm, wn);

#pragma unroll
    for (int mt = 0; mt < 2; ++mt) {
        int row = m0 + wm + mt * 16 + (lane >> 2);
#pragma unroll
        for (int nt = 0; nt < 4; ++nt) {
            int col = n0 + wn + nt * 8 + (lane & 3) * 2;
            *(float2*)(Y + (size_t)row * CC + col)       = make_float2(acc[mt][nt][0], acc[mt][nt][1]);
            *(float2*)(Y + (size_t)(row + 8) * CC + col) = make_float2(acc[mt][nt][2], acc[mt][nt][3]);
        }
    }
}

// ---------------- launch -----------------------------------------------------
extern "C" void kernel_launch(void* const* d_in, const int* in_sizes, int n_in,
                              void* d_out, int out_size)
{
    (void)in_sizes; (void)n_in; (void)out_size;
    const float*         x     = (const float*)d_in[0];
    const float*         pos   = (const float*)d_in[1];
    const unsigned char* mask  = (const unsigned char*)d_in[2];
    const float*         Wqkv  = (const float*)d_in[3];
    const float*         Wout  = (const float*)d_in[4];
    const float*         Wpre  = (const float*)d_in[5];
    const float*         bpre  = (const float*)d_in[6];
    const float*         Wpost = (const float*)d_in[7];
    const float*         bpost = (const float*)d_in[8];
    float* y = (float*)d_out;

    float *v;
    __half *dots, *q, *k;
    __nv_bfloat16 *xh, *xl, *wqh, *wql, *woh, *wol;
    __nv_bfloat16 *oh, *ol;
    __half *vt, *attn;
    cudaGetSymbolAddress((void**)&v,    g_v);
    cudaGetSymbolAddress((void**)&dots, g_dots);
    cudaGetSymbolAddress((void**)&xh,  g_xh);
    cudaGetSymbolAddress((void**)&xl,  g_xl);
    cudaGetSymbolAddress((void**)&wqh, g_wqh);
    cudaGetSymbolAddress((void**)&wql, g_wql);
    cudaGetSymbolAddress((void**)&woh, g_woh);
    cudaGetSymbolAddress((void**)&wol, g_wol);
    cudaGetSymbolAddress((void**)&q,   g_qs);
    cudaGetSymbolAddress((void**)&k,   g_ks);
    cudaGetSymbolAddress((void**)&vt,  g_vt);
    cudaGetSymbolAddress((void**)&attn, g_attn);
    cudaGetSymbolAddress((void**)&oh,  g_outf_hi);
    cudaGetSymbolAddress((void**)&ol,  g_outf_lo);

    cudaFuncSetAttribute(qkv_mma_kernel,  cudaFuncAttributeMaxDynamicSharedMemorySize, PIPE_SMEM);
    cudaFuncSetAttribute(out_mma_kernel,  cudaFuncAttributeMaxDynamicSharedMemorySize, PIPE_SMEM);
    cudaFuncSetAttribute(dots_mma_kernel, cudaFuncAttributeMaxDynamicSharedMemorySize, DK_SMEM);
    cudaFuncSetAttribute(av_mma_kernel,   cudaFuncAttributeMaxDynamicSharedMemorySize, AVF_SMEM);

    split_kernel<<<(BB * NN * CC + 255) / 256, 256>>>(x, xh, xl, BB * NN * CC);
    split_wqkv_kernel<<<(FF * CC + 255) / 256, 256>>>(Wqkv, wqh, wql);
    split_kernel<<<(CC * HH * DD + 255) / 256, 256>>>(Wout, woh, wol, CC * HH * DD);

    qkv_mma_kernel<<<dim3(FF / 64, (BB * NN) / 128), 256, PIPE_SMEM>>>(xh, xl, wqh, wql, q, k, v);
    convert_v_kernel<<<dim3(NN / 64, BB * HH), 256>>>(v, vt);
    dots_mma_kernel<<<dim3(NN / 128, NN / 128, BB * HH), 256, DK_SMEM>>>(q, k, dots);
    mix_softmax_kernel<<<dim3(BB, NN), 512>>>(dots, pos, mask, Wpre, bpre, Wpost, bpost, attn);
    av_mma_kernel<<<dim3(NN / 128, BB * HH), 256, AVF_SMEM>>>(attn, vt, oh, ol);
    out_mma_kernel<<<dim3(CC / 64, (BB * NN) / 128), 256, PIPE_SMEM>>>(oh, ol, woh, wol, y);
}

// round 17
// speedup vs baseline: 1.8567x; 1.1090x over previous
#include <cuda_runtime.h>
#include <cuda_bf16.h>
#include <cuda_fp16.h>
#include <math.h>
#include <float.h>
#include <stdint.h>

// Problem constants
#define BB 2
#define NN 2048
#define CC 512
#define HH 8
#define DD 64
#define FF 1536   // 3*H*D

// ==================== scratch (device globals) ====================
__device__ float g_v[BB * HH * NN * DD];
__device__ __align__(256) __half g_dots[(size_t)BB * HH * NN * NN];   // 128 MiB fp16
__device__ __align__(256) __nv_bfloat16 g_xh[BB * NN * CC];
__device__ __align__(256) __nv_bfloat16 g_xl[BB * NN * CC];
__device__ __align__(256) __nv_bfloat16 g_wqh[FF * CC];        // permuted f' = s*512+h*64+d
__device__ __align__(256) __nv_bfloat16 g_wql[FF * CC];
__device__ __align__(256) __nv_bfloat16 g_woh[CC * HH * DD];
__device__ __align__(256) __nv_bfloat16 g_wol[CC * HH * DD];
__device__ __align__(256) __half g_qs[BB * HH * NN * DD];      // fp16 single (scale folded)
__device__ __align__(256) __half g_ks[BB * HH * NN * DD];      // fp16 single
__device__ __align__(256) __half g_vt[BB * HH * DD * NN];      // [bh][d][n] fp16 single
__device__ __align__(256) __half g_attn[(size_t)BB * HH * NN * NN];   // 128 MiB fp16 single
__device__ __align__(256) __nv_bfloat16 g_outf_hi[BB * NN * (HH * DD)];
__device__ __align__(256) __nv_bfloat16 g_outf_lo[BB * NN * (HH * DD)];

// ==================== helpers ====================
__device__ __forceinline__ uint32_t smem_u32(const void* p) {
    uint32_t a;
    asm("{ .reg .u64 t; cvta.to.shared.u64 t, %1; cvt.u32.u64 %0, t; }" : "=r"(a) : "l"(p));
    return a;
}
__device__ __forceinline__ uint32_t sw64(uint32_t off)  { return off ^ ((off >> 3) & 0x30); }
__device__ __forceinline__ uint32_t sw128(uint32_t off) { return off ^ ((off >> 3) & 0x70); }

__device__ __forceinline__ void ldsm4(uint32_t (&r)[4], uint32_t addr) {
    asm volatile("ldmatrix.sync.aligned.m8n8.x4.shared.b16 {%0,%1,%2,%3}, [%4];"
        : "=r"(r[0]), "=r"(r[1]), "=r"(r[2]), "=r"(r[3]) : "r"(addr));
}
__device__ __forceinline__ void mma16816(float (&c)[4], const uint32_t (&a)[4],
                                         uint32_t b0, uint32_t b1) {
    asm volatile("mma.sync.aligned.m16n8k16.row.col.f32.bf16.bf16.f32 "
        "{%0,%1,%2,%3}, {%4,%5,%6,%7}, {%8,%9}, {%0,%1,%2,%3};"
        : "+f"(c[0]), "+f"(c[1]), "+f"(c[2]), "+f"(c[3])
        : "r"(a[0]), "r"(a[1]), "r"(a[2]), "r"(a[3]), "r"(b0), "r"(b1));
}
__device__ __forceinline__ void mma16816h(float (&c)[4], const uint32_t (&a)[4],
                                          uint32_t b0, uint32_t b1) {
    asm volatile("mma.sync.aligned.m16n8k16.row.col.f32.f16.f16.f32 "
        "{%0,%1,%2,%3}, {%4,%5,%6,%7}, {%8,%9}, {%0,%1,%2,%3};"
        : "+f"(c[0]), "+f"(c[1]), "+f"(c[2]), "+f"(c[3])
        : "r"(a[0]), "r"(a[1]), "r"(a[2]), "r"(a[3]), "r"(b0), "r"(b1));
}
__device__ __forceinline__ void cp16(uint32_t saddr, const void* gptr) {
    asm volatile("cp.async.cg.shared.global [%0], [%1], 16;" :: "r"(saddr), "l"(gptr));
}
#define CP_COMMIT() asm volatile("cp.async.commit_group;" ::: "memory")
__device__ __forceinline__ void cp_wait_dyn(int pend) {
    if (pend >= 2)      asm volatile("cp.async.wait_group 2;" ::: "memory");
    else if (pend == 1) asm volatile("cp.async.wait_group 1;" ::: "memory");
    else                asm volatile("cp.async.wait_group 0;" ::: "memory");
}

// ==================== bf16 pipelined core (CTA 128x64, Kc=32, SW64) ===========
#define SA_H 0
#define SA_L 8192
#define SB_H 16384
#define SB_L 20480
#define ST_STRIDE 24576
#define PIPE_SMEM (3 * ST_STRIDE)

__device__ __forceinline__ void load_stage(
    uint32_t st, const __nv_bfloat16* __restrict__ AH, const __nv_bfloat16* __restrict__ AL,
    int lda, int m0, const __nv_bfloat16* __restrict__ BH, const __nv_bfloat16* __restrict__ BL,
    int ldb, int n0, int k0)
{
    const int t = threadIdx.x;
#pragma unroll
    for (int rep = 0; rep < 2; ++rep) {
        int idx = t + rep * 256;
        int r = idx >> 2, c4 = idx & 3;
        uint32_t off = sw64(r * 64 + c4 * 16);
        size_t ga = (size_t)(m0 + r) * lda + k0 + c4 * 8;
        cp16(st + SA_H + off, AH + ga);
        cp16(st + SA_L + off, AL + ga);
    }
    {
        int r = t >> 2, c4 = t & 3;
        uint32_t off = sw64(r * 64 + c4 * 16);
        size_t gb = (size_t)(n0 + r) * ldb + k0 + c4 * 8;
        cp16(st + SB_H + off, BH + gb);
        cp16(st + SB_L + off, BL + gb);
    }
}

__device__ __forceinline__ void compute_stage(uint32_t st, float (&acc)[2][4][4],
                                              int lane, int wm, int wn)
{
#pragma unroll
    for (int ks = 0; ks < 2; ++ks) {
        uint32_t aH[2][4], aL[2][4];
#pragma unroll
        for (int mt = 0; mt < 2; ++mt) {
            uint32_t row = wm + mt * 16 + (lane & 15);
            uint32_t so = sw64(row * 64 + ks * 32 + (lane >> 4) * 16);
            ldsm4(aH[mt], st + SA_H + so);
            ldsm4(aL[mt], st + SA_L + so);
        }
        uint32_t bH[2][4], bL[2][4];
#pragma unroll
        for (int np = 0; np < 2; ++np) {
            uint32_t row = wn + np * 16 + (lane & 7) + ((lane >> 4) << 3);
            uint32_t so = sw64(row * 64 + ks * 32 + ((lane >> 3) & 1) * 16);
            ldsm4(bH[np], st + SB_H + so);
            ldsm4(bL[np], st + SB_L + so);
        }
#pragma unroll
        for (int mt = 0; mt < 2; ++mt)
#pragma unroll
            for (int nt = 0; nt < 4; ++nt) {
                uint32_t b0h = bH[nt >> 1][(nt & 1) * 2], b1h = bH[nt >> 1][(nt & 1) * 2 + 1];
                uint32_t b0l = bL[nt >> 1][(nt & 1) * 2], b1l = bL[nt >> 1][(nt & 1) * 2 + 1];
                mma16816(acc[mt][nt], aH[mt], b0h, b1h);
                mma16816(acc[mt][nt], aH[mt], b0l, b1l);
                mma16816(acc[mt][nt], aL[mt], b0h, b1h);
            }
    }
}

__device__ __forceinline__ void mma_pipeline(
    const __nv_bfloat16* __restrict__ AH, const __nv_bfloat16* __restrict__ AL, int lda, int m0,
    const __nv_bfloat16* __restrict__ BH, const __nv_bfloat16* __restrict__ BL, int ldb, int n0,
    int K, uint32_t sb, float (&acc)[2][4][4], int lane, int wm, int wn)
{
    const int nk = K / 32;
    load_stage(sb, AH, AL, lda, m0, BH, BL, ldb, n0, 0);
    CP_COMMIT();
    if (nk > 1) {
        load_stage(sb + ST_STRIDE, AH, AL, lda, m0, BH, BL, ldb, n0, 32);
        CP_COMMIT();
    }
    for (int kc = 0; kc < nk; ++kc) {
        if (kc + 2 < nk) {
            load_stage(sb + ((kc + 2) % 3) * ST_STRIDE, AH, AL, lda, m0, BH, BL, ldb, n0,
                       (kc + 2) * 32);
            CP_COMMIT();
        }
        int pend = (nk < kc + 3 ? nk : kc + 3) - (kc + 1);
        cp_wait_dyn(pend);
        __syncthreads();
        compute_stage(sb + (kc % 3) * ST_STRIDE, acc, lane, wm, wn);
        __syncthreads();
    }
}

// ---------------- K0a: plain split fp32 -> bf16 hi/lo ----------------
__global__ void split_kernel(const float* __restrict__ in, __nv_bfloat16* __restrict__ hi,
                             __nv_bfloat16* __restrict__ lo, int n)
{
    int i = blockIdx.x * 256 + threadIdx.x;
    if (i < n) {
        float v = in[i];
        __nv_bfloat16 h = __float2bfloat16(v);
        hi[i] = h;
        lo[i] = __float2bfloat16(v - __bfloat162float(h));
    }
}

// ---------------- K0b: permuted+scaled split of Wqkv ----------------
__global__ void split_wqkv_kernel(const float* __restrict__ W,
                                  __nv_bfloat16* __restrict__ hi, __nv_bfloat16* __restrict__ lo)
{
    int i = blockIdx.x * 256 + threadIdx.x;
    if (i < FF * CC) {
        int f = i >> 9;
        int c = i & 511;
        int h = f / 192;
        int r = f - h * 192;
        int d = r / 3;
        int s = r - d * 3;
        int fp = s * 512 + h * 64 + d;
        float v = W[i] * (s == 0 ? 0.125f : 1.0f);
        __nv_bfloat16 hb = __float2bfloat16(v);
        hi[fp * 512 + c] = hb;
        lo[fp * 512 + c] = __float2bfloat16(v - __bfloat162float(hb));
    }
}

// ---------------- K1: QKV projection + coalesced scatter ----------------
__global__ __launch_bounds__(256, 2)
void qkv_mma_kernel(const __nv_bfloat16* __restrict__ XH, const __nv_bfloat16* __restrict__ XL,
                    const __nv_bfloat16* __restrict__ WH, const __nv_bfloat16* __restrict__ WL,
                    __half* __restrict__ Q, __half* __restrict__ K,
                    float* __restrict__ V)
{
    extern __shared__ __align__(128) char smem[];
    const uint32_t sb = smem_u32(smem);
    const int m0 = blockIdx.y * 128;
    const int n0 = blockIdx.x * 64;
    const int s = n0 >> 9;
    const int h = (n0 >> 6) & 7;
    const int lane = threadIdx.x & 31, warp = threadIdx.x >> 5;
    const int wm = (warp & 3) * 32, wn = (warp >> 2) * 32;
    float acc[2][4][4] = {};
    mma_pipeline(XH, XL, CC, m0, WH, WL, CC, n0, CC, sb, acc, lane, wm, wn);

#pragma unroll
    for (int mt = 0; mt < 2; ++mt) {
#pragma unroll
        for (int half = 0; half < 2; ++half) {
            int m = m0 + wm + mt * 16 + (lane >> 2) + half * 8;
            int b = m >> 11, n = m & 2047;
            size_t base = (((size_t)b * HH + h) * NN + n) * DD;
#pragma unroll
            for (int nt = 0; nt < 4; ++nt) {
                int d = wn + nt * 8 + (lane & 3) * 2;
                float v0 = acc[mt][nt][half * 2 + 0];
                float v1 = acc[mt][nt][half * 2 + 1];
                if (s == 2) {
                    *(float2*)(V + base + d) = make_float2(v0, v1);
                } else {
                    __half2 hp; hp.x = __float2half(v0); hp.y = __float2half(v1);
                    if (s == 0) *(__half2*)(Q + base + d) = hp;
                    else        *(__half2*)(K + base + d) = hp;
                }
            }
        }
    }
}

// ---------------- K1b: transpose V -> vt (fp16 single) -----------------------
__global__ void convert_v_kernel(const float* __restrict__ V, __half* __restrict__ VT)
{
    __shared__ float ts[64][65];
    const int bh = blockIdx.y;
    const int n0 = blockIdx.x * 64;
    const int t = threadIdx.x;
    const size_t base = ((size_t)bh * NN + n0) * DD;
    for (int idx = t; idx < 64 * 64; idx += 256)
        ts[idx >> 6][idx & 63] = V[base + idx];
    __syncthreads();
    for (int idx = t; idx < 64 * 64; idx += 256) {
        int d = idx >> 6, c = idx & 63;
        VT[((size_t)bh * DD + d) * NN + n0 + c] = __float2half(ts[c][d]);
    }
}

// ---------------- K2: dots = q(f16) @ k(f16)^T, 1 combo ----------------------
#define DT_A 0
#define DT_B 16384
#define DK_SMEM 32768

__global__ __launch_bounds__(256, 2)
void dots_mma_kernel(const __half* __restrict__ Q, const __half* __restrict__ K,
                     __half* __restrict__ Dots)
{
    extern __shared__ __align__(128) char smem[];
    const uint32_t sb = smem_u32(smem);
    const int t = threadIdx.x;
    const int lane = t & 31, warp = t >> 5;
    const int wm = (warp & 3) * 32;
    const int wn = (warp >> 2) * 64;
    const int bh = blockIdx.z;
    const int m0 = blockIdx.y * 128;
    const int n0 = blockIdx.x * 128;

    const __half* q = Q + ((size_t)bh * NN + m0) * DD;
    const __half* k = K + ((size_t)bh * NN + n0) * DD;
#pragma unroll
    for (int rep = 0; rep < 4; ++rep) {
        int idx = t + rep * 256;
        int r = idx >> 3, c8 = idx & 7;
        uint32_t off = sw128(r * 128 + c8 * 16);
        int go = r * DD + c8 * 8;
        cp16(sb + DT_A + off, q + go);
        cp16(sb + DT_B + off, k + go);
    }
    CP_COMMIT();
    asm volatile("cp.async.wait_group 0;" ::: "memory");
    __syncthreads();

    float acc[2][8][4] = {};
#pragma unroll
    for (int ks = 0; ks < 4; ++ks) {
        uint32_t a[2][4];
#pragma unroll
        for (int mt = 0; mt < 2; ++mt) {
            uint32_t row = wm + mt * 16 + (lane & 15);
            uint32_t so = sw128(row * 128 + ks * 32 + (lane >> 4) * 16);
            ldsm4(a[mt], sb + DT_A + so);
        }
        uint32_t bb[4][4];
#pragma unroll
        for (int np = 0; np < 4; ++np) {
            uint32_t row = wn + np * 16 + (lane & 7) + ((lane >> 4) << 3);
            uint32_t so = sw128(row * 128 + ks * 32 + ((lane >> 3) & 1) * 16);
            ldsm4(bb[np], sb + DT_B + so);
        }
#pragma unroll
        for (int mt = 0; mt < 2; ++mt)
#pragma unroll
            for (int nt = 0; nt < 8; ++nt)
                mma16816h(acc[mt][nt], a[mt],
                          bb[nt >> 1][(nt & 1) * 2], bb[nt >> 1][(nt & 1) * 2 + 1]);
    }

    __half* C = Dots + ((size_t)bh * NN + m0) * NN + n0;
#pragma unroll
    for (int mt = 0; mt < 2; ++mt) {
        int row = wm + mt * 16 + (lane >> 2);
#pragma unroll
        for (int nt = 0; nt < 8; ++nt) {
            int col = wn + nt * 8 + (lane & 3) * 2;
            __half2 h0; h0.x = __float2half(acc[mt][nt][0]); h0.y = __float2half(acc[mt][nt][1]);
            __half2 h1; h1.x = __float2half(acc[mt][nt][2]); h1.y = __float2half(acc[mt][nt][3]);
            *(__half2*)(C + (size_t)row * NN + col)       = h0;
            *(__half2*)(C + (size_t)(row + 8) * NN + col) = h1;
        }
    }
}

// ---------------- K3: fused pre-mix(h2) + pos + mask + softmax + post-mix(h2) -
__global__ __launch_bounds__(512)
void mix_softmax_kernel(const __half* __restrict__ Dots,
                        const float* __restrict__ Pos,
                        const unsigned char* __restrict__ Mask,
                        const float* __restrict__ Wpre,
                        const float* __restrict__ Bpre,
                        const float* __restrict__ Wpost,
                        const float* __restrict__ Bpost,
                        __half* __restrict__ Attn)
{
    __shared__ __half2 wpre2[64], wpost2[64], bpre2[8], bpost2[8];
    __shared__ float red[8][16];
    __shared__ float gstat[8];
    const int b = blockIdx.x;
    const int i = blockIdx.y;
    const int t = threadIdx.x;
    const int lane = t & 31, warp = t >> 5;
    if (t < 64) {
        wpre2[t]  = __float2half2_rn(Wpre[t]);
        wpost2[t] = __float2half2_rn(Wpost[t]);
    }
    if (t >= 64 && t < 72) {
        bpre2[t - 64]  = __float2half2_rn(Bpre[t - 64]);
        bpost2[t - 64] = __float2half2_rn(Bpost[t - 64]);
    }
    __syncthreads();

    const int j0 = t * 4;
    // load dots as half2 pairs: v2[pair][h] covers cols (j0+2p, j0+2p+1)
    __half2 v2[2][8];
#pragma unroll
    for (int h = 0; h < 8; ++h) {
        const __half2* src = (const __half2*)(Dots + (((size_t)b * HH + h) * NN + i) * NN + j0);
        v2[0][h] = src[0];
        v2[1][h] = src[1];
    }
    // pre-mix in half2
    __half2 m2[2][8];
#pragma unroll
    for (int c2 = 0; c2 < 2; ++c2)
#pragma unroll
        for (int g = 0; g < 8; ++g) {
            __half2 a = bpre2[g];
#pragma unroll
            for (int h = 0; h < 8; ++h) a = __hfma2(wpre2[g * 8 + h], v2[c2][h], a);
            m2[c2][g] = a;
        }
    // pos(fp32) + mask + exp (no max subtraction: logits bounded)
    uchar4 mk4 = *(const uchar4*)(Mask + ((size_t)b * NN + i) * NN + j0);
    bool mb[4] = {mk4.x != 0, mk4.y != 0, mk4.z != 0, mk4.w != 0};
    float p[4][8];
    float lsum[8];
#pragma unroll
    for (int g = 0; g < 8; ++g) {
        float4 p4 = *(const float4*)(Pos + ((size_t)g * NN + i) * NN + j0);
        float2 a0 = __half22float2(m2[0][g]);
        float2 a1 = __half22float2(m2[1][g]);
        float vals[4] = {a0.x + p4.x, a0.y + p4.y, a1.x + p4.z, a1.y + p4.w};
        float s = 0.f;
#pragma unroll
        for (int c = 0; c < 4; ++c) {
            float e = mb[c] ? 0.0f : __expf(vals[c]);
            p[c][g] = e;
            s += e;
        }
        lsum[g] = s;
    }
    // block sum per g over 16 warps
#pragma unroll
    for (int g = 0; g < 8; ++g) {
        float s = lsum[g];
#pragma unroll
        for (int o = 16; o > 0; o >>= 1) s += __shfl_xor_sync(0xffffffffu, s, o);
        if (lane == 0) red[g][warp] = s;
    }
    __syncthreads();
    if (t < 8) {
        float s = 0.f;
#pragma unroll
        for (int w = 0; w < 16; ++w) s += red[t][w];
        gstat[t] = 1.0f / s;
    }
    __syncthreads();
    // normalize, pack to half2
    __half2 ph2[2][8];
#pragma unroll
    for (int h = 0; h < 8; ++h) {
        float inv = gstat[h];
        ph2[0][h] = __floats2half2_rn(p[0][h] * inv, p[1][h] * inv);
        ph2[1][h] = __floats2half2_rn(p[2][h] * inv, p[3][h] * inv);
    }
    // post-mix in half2, direct store
#pragma unroll
    for (int c2 = 0; c2 < 2; ++c2) {
#pragma unroll
        for (int g = 0; g < 8; ++g) {
            __half2 a = bpost2[g];
#pragma unroll
            for (int h = 0; h < 8; ++h) a = __hfma2(wpost2[g * 8 + h], ph2[c2][h], a);
            size_t ofs = (((size_t)b * HH + g) * NN + i) * NN + j0 + c2 * 2;
            *(__half2*)(Attn + ofs) = a;
        }
    }
}

// ---------------- K4: out = attn(f16) @ v(f16 single), 1 combo ----------------
#define AVF_A  0
#define AVF_B  16384
#define AVF_STRIDE 24576
#define AVF_SMEM (3 * AVF_STRIDE)

__device__ __forceinline__ void av_load_stage(uint32_t st,
    const __half* __restrict__ A, const __half* __restrict__ V, int j0)
{
    const int t = threadIdx.x;
#pragma unroll
    for (int rep = 0; rep < 4; ++rep) {
        int idx = t + rep * 256;
        int r = idx >> 3, c8 = idx & 7;
        uint32_t off = sw128(r * 128 + c8 * 16);
        cp16(st + AVF_A + off, A + (size_t)r * NN + j0 + c8 * 8);
    }
#pragma unroll
    for (int rep = 0; rep < 2; ++rep) {
        int idx = t + rep * 256;
        int r = idx >> 3, c8 = idx & 7;
        uint32_t off = sw128(r * 128 + c8 * 16);
        cp16(st + AVF_B + off, V + (size_t)r * NN + j0 + c8 * 8);
    }
}

__global__ __launch_bounds__(256, 2)
void av_mma_kernel(const __half* __restrict__ Attn, const __half* __restrict__ VT,
                   __nv_bfloat16* __restrict__ OutH, __nv_bfloat16* __restrict__ OutL)
{
    extern __shared__ __align__(128) char smem[];
    const uint32_t sb = smem_u32(smem);
    const int lane = threadIdx.x & 31, warp = threadIdx.x >> 5;
    const int wm = (warp & 3) * 32, wn = (warp >> 2) * 32;
    const int bh = blockIdx.y;
    const int b = bh >> 3, h = bh & 7;
    const int m0 = blockIdx.x * 128;

    const __half* A = Attn + ((size_t)bh * NN + m0) * NN;
    const __half* V = VT + (size_t)bh * DD * NN;

    float acc[2][4][4] = {};
    const int nk = 32;
    av_load_stage(sb, A, V, 0); CP_COMMIT();
    av_load_stage(sb + AVF_STRIDE, A, V, 64); CP_COMMIT();

    for (int kc = 0; kc < nk; ++kc) {
        if (kc + 2 < nk) {
            av_load_stage(sb + ((kc + 2) % 3) * AVF_STRIDE, A, V, (kc + 2) * 64);
            CP_COMMIT();
        }
        int pend = (nk < kc + 3 ? nk : kc + 3) - (kc + 1);
        cp_wait_dyn(pend);
        __syncthreads();
        const uint32_t st = sb + (kc % 3) * AVF_STRIDE;
#pragma unroll
        for (int ks = 0; ks < 4; ++ks) {
            uint32_t a[2][4];
#pragma unroll
            for (int mt = 0; mt < 2; ++mt) {
                uint32_t row = wm + mt * 16 + (lane & 15);
                uint32_t so = sw128(row * 128 + ks * 32 + (lane >> 4) * 16);
                ldsm4(a[mt], st + AVF_A + so);
            }
            uint32_t bb[2][4];
#pragma unroll
            for (int np = 0; np < 2; ++np) {
                uint32_t row = wn + np * 16 + (lane & 7) + ((lane >> 4) << 3);
                uint32_t so = sw128(row * 128 + ks * 32 + ((lane >> 3) & 1) * 16);
                ldsm4(bb[np], st + AVF_B + so);
            }
#pragma unroll
            for (int mt = 0; mt < 2; ++mt)
#pragma unroll
                for (int nt = 0; nt < 4; ++nt)
                    mma16816h(acc[mt][nt], a[mt],
                              bb[nt >> 1][(nt & 1) * 2], bb[nt >> 1][(nt & 1) * 2 + 1]);
        }
        __syncthreads();
    }

#pragma unroll
    for (int mt = 0; mt < 2; ++mt) {
        int row = m0 + wm + mt * 16 + (lane >> 2);
#pragma unroll
        for (int half = 0; half < 2; ++half) {
            size_t rb = ((size_t)b * NN + row + half * 8) * (HH * DD) + h * DD;
#pragma unroll
            for (int nt = 0; nt < 4; ++nt) {
                int col = wn + nt * 8 + (lane & 3) * 2;
                float v0 = acc[mt][nt][half * 2 + 0];
                float v1 = acc[mt][nt][half * 2 + 1];
                __nv_bfloat16 h0 = __float2bfloat16(v0);
                __nv_bfloat16 h1 = __float2bfloat16(v1);
                __nv_bfloat162 hp; hp.x = h0; hp.y = h1;
                __nv_bfloat162 lp;
                lp.x = __float2bfloat16(v0 - __bfloat162float(h0));
                lp.y = __float2bfloat16(v1 - __bfloat162float(h1));
                *(__nv_bfloat162*)(OutH + rb + col) = hp;
                *(__nv_bfloat162*)(OutL + rb + col) = lp;
            }
        }
    }
}

// ---------------- K5: final projection y = outf @ Wout^T ---------------------
__global__ __launch_bounds__(256, 2)
void out_mma_kernel(const __nv_bfloat16* __restrict__ OH, const __nv_bfloat16* __restrict__ OL,
                    const __nv_bfloat16* __restrict__ WH, const __nv_bfloat16* __restrict__ WL,
                    float* __restrict__ Y)
{
    extern __shared__ __align__(128) char smem[];
    const uint32_t sb = smem_u32(smem);
    const int m0 = blockIdx.y * 128;
    const int n0 = blockIdx.x * 64;
    const int lane = threadIdx.x & 31, warp = threadIdx.x >> 5;
    const int wm = (warp & 3) * 32, wn = (warp >> 2) * 32;
    float acc[2][4][4] = {};
    mma_pipeline(OH, OL, HH * DD, m0, WH, WL, HH * DD, n0, HH * DD, sb, acc, lane, wm, wn);

#pragma unroll
    for (int mt = 0; mt < 2; ++mt) {
        int row = m0 + wm + mt * 16 + (lane >> 2);
#pragma unroll
        for (int nt = 0; nt < 4; ++nt) {
            int col = n0 + wn + nt * 8 + (lane & 3) * 2;
            *(float2*)(Y + (size_t)row * CC + col)       = make_float2(acc[mt][nt][0], acc[mt][nt][1]);
            *(float2*)(Y + (size_t)(row + 8) * CC + col) = make_float2(acc[mt][nt][2], acc[mt][nt][3]);
        }
    }
}

// ---------------- launch -----------------------------------------------------
extern "C" void kernel_launch(void* const* d_in, const int* in_sizes, int n_in,
                              void* d_out, int out_size)
{
    (void)in_sizes; (void)n_in; (void)out_size;
    const float*         x     = (const float*)d_in[0];
    const float*         pos   = (const float*)d_in[1];
    const unsigned char* mask  = (const unsigned char*)d_in[2];
    const float*         Wqkv  = (const float*)d_in[3];
    const float*         Wout  = (const float*)d_in[4];
    const float*         Wpre  = (const float*)d_in[5];
    const float*         bpre  = (const float*)d_in[6];
    const float*         Wpost = (const float*)d_in[7];
    const float*         bpost = (const float*)d_in[8];
    float* y = (float*)d_out;

    float *v;
    __half *dots, *q, *k;
    __nv_bfloat16 *xh, *xl, *wqh, *wql, *woh, *wol;
    __nv_bfloat16 *oh, *ol;
    __half *vt, *attn;
    cudaGetSymbolAddress((void**)&v,    g_v);
    cudaGetSymbolAddress((void**)&dots, g_dots);
    cudaGetSymbolAddress((void**)&xh,  g_xh);
    cudaGetSymbolAddress((void**)&xl,  g_xl);
    cudaGetSymbolAddress((void**)&wqh, g_wqh);
    cudaGetSymbolAddress((void**)&wql, g_wql);
    cudaGetSymbolAddress((void**)&woh, g_woh);
    cudaGetSymbolAddress((void**)&wol, g_wol);
    cudaGetSymbolAddress((void**)&q,   g_qs);
    cudaGetSymbolAddress((void**)&k,   g_ks);
    cudaGetSymbolAddress((void**)&vt,  g_vt);
    cudaGetSymbolAddress((void**)&attn, g_attn);
    cudaGetSymbolAddress((void**)&oh,  g_outf_hi);
    cudaGetSymbolAddress((void**)&ol,  g_outf_lo);

    cudaFuncSetAttribute(qkv_mma_kernel,  cudaFuncAttributeMaxDynamicSharedMemorySize, PIPE_SMEM);
    cudaFuncSetAttribute(out_mma_kernel,  cudaFuncAttributeMaxDynamicSharedMemorySize, PIPE_SMEM);
    cudaFuncSetAttribute(dots_mma_kernel, cudaFuncAttributeMaxDynamicSharedMemorySize, DK_SMEM);
    cudaFuncSetAttribute(av_mma_kernel,   cudaFuncAttributeMaxDynamicSharedMemorySize, AVF_SMEM);

    split_kernel<<<(BB * NN * CC + 255) / 256, 256>>>(x, xh, xl, BB * NN * CC);
    split_wqkv_kernel<<<(FF * CC + 255) / 256, 256>>>(Wqkv, wqh, wql);
    split_kernel<<<(CC * HH * DD + 255) / 256, 256>>>(Wout, woh, wol, CC * HH * DD);

    qkv_mma_kernel<<<dim3(FF / 64, (BB * NN) / 128), 256, PIPE_SMEM>>>(xh, xl, wqh, wql, q, k, v);
    convert_v_kernel<<<dim3(NN / 64, BB * HH), 256>>>(v, vt);
    dots_mma_kernel<<<dim3(NN / 128, NN / 128, BB * HH), 256, DK_SMEM>>>(q, k, dots);
    mix_softmax_kernel<<<dim3(BB, NN), 512>>>(dots, pos, mask, Wpre, bpre, Wpost, bpost, attn);
    av_mma_kernel<<<dim3(NN / 128, BB * HH), 256, AVF_SMEM>>>(attn, vt, oh, ol);
    out_mma_kernel<<<dim3(CC / 64, (BB * NN) / 128), 256, PIPE_SMEM>>>(oh, ol, woh, wol, y);
}